// round 14
// baseline (speedup 1.0000x reference)
#include <cuda_runtime.h>
#include <cuda_fp16.h>
#include <math.h>
#include <stdint.h>

#define BB 2
#define SS 2048
#define DD 1024
#define HH 16
#define DHD 64
#define NROWS (BB*SS)          /* 4096 */
#define ROPE_LOG2C 0.4152410118609203f   /* log2(10000)/32 */
#define SM_SCALE_LOG2E 0.1803368801111204f  /* 0.125 * log2(e) */

/* Scratch (allocation-free rule) — all fp16 */
__device__ __half g_xh[(size_t)NROWS*DD];
__device__ __half g_wq[DD*DD];     /* transposed, fp16 */
__device__ __half g_wk[DD*DD];
__device__ __half g_wv[DD*DD];
__device__ __half g_wo[DD*DD];
__device__ __half g_q[BB*HH*SS*DHD];       /* [b,h,s,d], pre-scaled by 0.125*log2e */
__device__ __half g_k[BB*HH*SS*DHD];       /* [b,h,s,d] */
__device__ __half g_v[BB*HH*SS*DHD];       /* [b,h,d,s] TRANSPOSED */
__device__ __half g_ctx[(size_t)NROWS*DD]; /* [b*s, d]  */

__device__ __forceinline__ uint32_t smem_u32_of(const void* p) {
    uint32_t a;
    asm("{ .reg .u64 t; cvta.to.shared.u64 t, %1; cvt.u32.u64 %0, t; }" : "=r"(a) : "l"(p));
    return a;
}
__device__ __forceinline__ uint32_t ldh2(const __half* p) {
    return *reinterpret_cast<const uint32_t*>(p);
}
/* pack (lo,hi) to fp16x2 and take exp2 in fp16x2 — one MUFU for two values */
__device__ __forceinline__ uint32_t ex2_h2(float lo, float hi) {
    uint32_t r;
    asm("{\n\t.reg .b32 t;\n\t"
        "cvt.rn.f16x2.f32 t, %2, %1;\n\t"
        "ex2.approx.f16x2 %0, t;\n\t}"
        : "=r"(r) : "f"(lo), "f"(hi));
    return r;
}

#define MMA_F16(c, a, b0, b1) \
    asm volatile("mma.sync.aligned.m16n8k16.row.col.f32.f16.f16.f32 " \
        "{%0,%1,%2,%3}, {%4,%5,%6,%7}, {%8,%9}, {%0,%1,%2,%3};" \
        : "+f"((c)[0]), "+f"((c)[1]), "+f"((c)[2]), "+f"((c)[3]) \
        : "r"((a)[0]), "r"((a)[1]), "r"((a)[2]), "r"((a)[3]), \
          "r"(b0), "r"(b1))

#define LDSM4(d0, d1, d2, d3, addr) \
    asm volatile("ldmatrix.sync.aligned.m8n8.x4.shared.b16 {%0,%1,%2,%3}, [%4];" \
        : "=r"(d0), "=r"(d1), "=r"(d2), "=r"(d3) : "r"(addr))

#define CP16(dst, src) \
    asm volatile("cp.async.cg.shared.global [%0], [%1], 16;" :: "r"(dst), "l"(src))
#define CPCOMMIT() asm volatile("cp.async.commit_group;" ::: "memory")
#define CPWAIT(n)  asm volatile("cp.async.wait_group %0;" :: "n"(n) : "memory")

/* ================================================================== */
/* Pre-pass 1: X -> fp16. 8 floats / thread.                          */
/* ================================================================== */
__global__ void round_x_kernel(const float* __restrict__ X)
{
    const size_t idx = (size_t)(blockIdx.x * 256 + threadIdx.x) * 8;
    float4 v0 = *reinterpret_cast<const float4*>(X + idx);
    float4 v1 = *reinterpret_cast<const float4*>(X + idx + 4);
    __half2* ph = reinterpret_cast<__half2*>(g_xh + idx);
    ph[0] = __floats2half2_rn(v0.x, v0.y);
    ph[1] = __floats2half2_rn(v0.z, v0.w);
    ph[2] = __floats2half2_rn(v1.x, v1.y);
    ph[3] = __floats2half2_rn(v1.z, v1.w);
}

/* ================================================================== */
/* Pre-pass 2: transpose + fp16-convert the 4 weight matrices.        */
/* ================================================================== */
__global__ void wtrans_kernel(const float* __restrict__ Wq,
                              const float* __restrict__ Wk,
                              const float* __restrict__ Wv,
                              const float* __restrict__ Wo)
{
    __shared__ float t[32][33];
    const int z = blockIdx.z;
    const float* src = (z == 0) ? Wq : ((z == 1) ? Wk : ((z == 2) ? Wv : Wo));
    __half* dst = (z == 0) ? g_wq : ((z == 1) ? g_wk : ((z == 2) ? g_wv : g_wo));
    const int r0 = blockIdx.y * 32, c0 = blockIdx.x * 32;
    const int tx = threadIdx.x, ty = threadIdx.y;
#pragma unroll
    for (int k = 0; k < 4; k++)
        t[ty + 8 * k][tx] = src[(size_t)(r0 + ty + 8 * k) * DD + c0 + tx];
    __syncthreads();
#pragma unroll
    for (int k = 0; k < 4; k++)
        dst[(size_t)(c0 + ty + 8 * k) * DD + r0 + tx] = __float2half_rn(t[tx][ty + 8 * k]);
}

/* ================================================================== */
/* GEMM fp16: CTA 128x128, 8 warps (warp tile 64x32), BK=32, 4-stage. */
/* ================================================================== */
#define GM_PITCH  40                        /* halves */
#define GM_ABYTES (128*GM_PITCH*2)          /* 10240 */
#define GM_STAGE  (2*GM_ABYTES)             /* 20480 */
#define GM_SMEM   (4 * GM_STAGE)            /* 81920 */

__device__ __forceinline__ void gemm_issue_stage(
    const __half* __restrict__ A, const __half* __restrict__ Wt,
    int row0, int col0, int s, int buf, uint32_t sm)
{
    const int tid = threadIdx.x;
    const uint32_t base = sm + (uint32_t)buf * GM_STAGE;
    const int r = tid >> 2, q = tid & 3;   /* r: 0..63, q: 16B chunk */
#pragma unroll
    for (int it = 0; it < 2; it++) {
        const int rr = r + it * 64;
        CP16(base + (uint32_t)(rr * (GM_PITCH*2) + q * 16),
             A + (size_t)(row0 + rr) * DD + s * 32 + q * 8);
        CP16(base + GM_ABYTES + (uint32_t)(rr * (GM_PITCH*2) + q * 16),
             Wt + (size_t)(col0 + rr) * DD + s * 32 + q * 8);
    }
}

__device__ __forceinline__ void gemm_h(
    const __half* __restrict__ A, const __half* __restrict__ Wt,
    int row0, int col0, char* smem, uint32_t sm, float acc[4][4][4])
{
    const int lane = threadIdx.x & 31, warp = threadIdx.x >> 5;
    const int wm = warp >> 2, wn = warp & 3;
    const int ar = lane >> 2, ac = lane & 3;

    gemm_issue_stage(A, Wt, row0, col0, 0, 0, sm); CPCOMMIT();
    gemm_issue_stage(A, Wt, row0, col0, 1, 1, sm); CPCOMMIT();
    gemm_issue_stage(A, Wt, row0, col0, 2, 2, sm); CPCOMMIT();

    for (int kt = 0; kt < 32; kt++) {
        CPWAIT(2);
        __syncthreads();
        if (kt + 3 < 32) gemm_issue_stage(A, Wt, row0, col0, kt + 3, (kt + 3) & 3, sm);
        CPCOMMIT();

        const __half* AsH = reinterpret_cast<const __half*>(smem + (size_t)(kt & 3) * GM_STAGE);
        const __half* BsH = AsH + 128 * GM_PITCH;

#pragma unroll
        for (int k16 = 0; k16 < 2; k16++) {
            const int colb = k16 * 16 + 2 * ac;
            uint32_t a[4][4], b[4][2];
#pragma unroll
            for (int i = 0; i < 4; i++) {
                const int m = wm * 64 + i * 16 + ar;
                a[i][0] = ldh2(AsH + m * GM_PITCH + colb);
                a[i][1] = ldh2(AsH + (m + 8) * GM_PITCH + colb);
                a[i][2] = ldh2(AsH + m * GM_PITCH + colb + 8);
                a[i][3] = ldh2(AsH + (m + 8) * GM_PITCH + colb + 8);
            }
#pragma unroll
            for (int j = 0; j < 4; j++) {
                const int n = wn * 32 + j * 8 + ar;
                b[j][0] = ldh2(BsH + n * GM_PITCH + colb);
                b[j][1] = ldh2(BsH + n * GM_PITCH + colb + 8);
            }
#pragma unroll
            for (int i = 0; i < 4; i++)
#pragma unroll
                for (int j = 0; j < 4; j++)
                    MMA_F16(acc[i][j], a[i], b[j][0], b[j][1]);
        }
    }
}

/* ------------------------------------------------------------------ */
__global__ void __launch_bounds__(256, 2)
qkv_h_kernel()
{
    extern __shared__ __align__(16) char smem[];
    const uint32_t sm = smem_u32_of(smem);
    const int which = blockIdx.z;
    const __half* __restrict__ Wt = (which == 0) ? g_wq : ((which == 1) ? g_wk : g_wv);
    const int row0 = blockIdx.y * 128, col0 = blockIdx.x * 128;

    float acc[4][4][4];
#pragma unroll
    for (int i = 0; i < 4; i++)
#pragma unroll
        for (int j = 0; j < 4; j++)
#pragma unroll
            for (int c = 0; c < 4; c++) acc[i][j][c] = 0.f;

    gemm_h(g_xh, Wt, row0, col0, smem, sm, acc);

    const int lane = threadIdx.x & 31, warp = threadIdx.x >> 5;
    const int wm = warp >> 2, wn = warp & 3;
    const int ar = lane >> 2, ac = lane & 3;
    const int h = (col0 >> 6) + (wn >> 1);   /* warp covers half a head */
    const int dhb = (wn & 1) * 32;

    if (which < 2) {
        __half* __restrict__ dst = (which == 0) ? g_q : g_k;
        const float post = (which == 0) ? SM_SCALE_LOG2E : 1.0f;
        /* this thread's 8 rows are base + 8t (same batch, consecutive s) */
        const int rowb = row0 + wm * 64 + ar;
        const int b_ = rowb >> 11, sbase = rowb & (SS - 1);
        __half* dhead = dst + ((size_t)(b_ * HH + h) * SS) * DHD;
#pragma unroll
        for (int j = 0; j < 4; j++) {
            const float freq = exp2f(-(float)((dhb >> 1) + j * 4 + ac) * ROPE_LOG2C);
            const int dh = dhb + j * 8 + 2 * ac;
            float sn, cs, sd, cd;
            sincosf((float)sbase * freq, &sn, &cs);
            sincosf(8.0f * freq, &sd, &cd);
#pragma unroll
            for (int t = 0; t < 8; t++) {
                const int i = t >> 1, half_ = t & 1;
                const float e = acc[i][j][half_ * 2], o = acc[i][j][half_ * 2 + 1];
                __half* drow = dhead + (size_t)(sbase + 8 * t) * DHD;
                *reinterpret_cast<__half2*>(&drow[dh]) =
                    __floats2half2_rn((e * cs - o * sn) * post,
                                      (e * sn + o * cs) * post);
                const float csn = cs * cd - sn * sd;
                sn = sn * cd + cs * sd;
                cs = csn;
            }
        }
    } else {
        /* V: store TRANSPOSED [b,h,d,s] */
#pragma unroll
        for (int i = 0; i < 4; i++) {
#pragma unroll
            for (int half_ = 0; half_ < 2; half_++) {
                const int row = row0 + wm * 64 + i * 16 + ar + half_ * 8;
                const int b_ = row >> 11, s = row & (SS - 1);
                __half* dbase = g_v + ((size_t)(b_ * HH + h)) * DHD * SS;
#pragma unroll
                for (int j = 0; j < 4; j++) {
                    const int dh = dhb + j * 8 + 2 * ac;
                    dbase[(size_t)dh * SS + s]       = __float2half_rn(acc[i][j][half_ * 2]);
                    dbase[(size_t)(dh + 1) * SS + s] = __float2half_rn(acc[i][j][half_ * 2 + 1]);
                }
            }
        }
    }
}

/* ------------------------------------------------------------------ */
__global__ void __launch_bounds__(256, 2)
out_h_kernel(const float* __restrict__ bo, float* __restrict__ out)
{
    extern __shared__ __align__(16) char smem[];
    const uint32_t sm = smem_u32_of(smem);
    const int row0 = blockIdx.y * 128, col0 = blockIdx.x * 128;

    float acc[4][4][4];
#pragma unroll
    for (int i = 0; i < 4; i++)
#pragma unroll
        for (int j = 0; j < 4; j++)
#pragma unroll
            for (int c = 0; c < 4; c++) acc[i][j][c] = 0.f;

    gemm_h(g_ctx, g_wo, row0, col0, smem, sm, acc);

    const int lane = threadIdx.x & 31, warp = threadIdx.x >> 5;
    const int wm = warp >> 2, wn = warp & 3;
    const int ar = lane >> 2, ac = lane & 3;

#pragma unroll
    for (int i = 0; i < 4; i++) {
        const int r = row0 + wm * 64 + i * 16 + ar;
#pragma unroll
        for (int j = 0; j < 4; j++) {
            const int col = col0 + wn * 32 + j * 8 + 2 * ac;
            const float bx = bo[col], by = bo[col + 1];
            *reinterpret_cast<float2*>(&out[(size_t)r * DD + col]) =
                make_float2(acc[i][j][0] + bx, acc[i][j][1] + by);
            *reinterpret_cast<float2*>(&out[(size_t)(r + 8) * DD + col]) =
                make_float2(acc[i][j][2] + bx, acc[i][j][3] + by);
        }
    }
}

/* ================================================================== */
/* Flash attention fp16 v5 (unchanged from R13): ldmatrix K/V frags;  */
/* P via fused f16x2 ex2; l via ones-column MMA; 3-buffer KV ring.    */
/* ================================================================== */
#define AT_PITCH  72                         /* halves */
#define AT_ROWB   (AT_PITCH*2)               /* 144 B */
#define AT_TILEB  (64*AT_ROWB)               /* 9216 */
#define AT_KOFF   AT_TILEB
#define AT_VOFF   (4*AT_TILEB)
#define AT_SMEM   (7*AT_TILEB)               /* 64512 */
#define H2_ONES   0x3C003C00u

__global__ void __launch_bounds__(128, 3)
attn_h_kernel()
{
    extern __shared__ __align__(16) char smem[];
    const uint32_t sm = smem_u32_of(smem);
    const int bh = blockIdx.y;
    const int qt = gridDim.x - 1 - blockIdx.x;   /* heavy-first */
    const __half* __restrict__ Q  = g_q + (size_t)bh * SS * DHD;
    const __half* __restrict__ K  = g_k + (size_t)bh * SS * DHD;
    const __half* __restrict__ Vt = g_v + (size_t)bh * DHD * SS;  /* [d][s] */

    const int tid = threadIdx.x;
    const int lane = tid & 31, warp = tid >> 5;
    const int ar = lane >> 2, ac = lane & 3;
    const int nk = qt + 1;
    const int mrow = warp * 16;

    const uint32_t lnrow = (uint32_t)(lane & 7);
    const uint32_t jsel  = (uint32_t)(lane >> 4);
    const uint32_t ksel  = (uint32_t)((lane >> 3) & 1) * 16;
    uint32_t lm_base[4];
#pragma unroll
    for (int t = 0; t < 4; t++)
        lm_base[t] = ((2 * t + jsel) * 8 + lnrow) * AT_ROWB + ksel;

    auto issue_kv = [&](int kt, int buf) {
#pragma unroll
        for (int it = 0; it < 4; it++) {
            const int idx = tid + it * 128;
            const int r = idx >> 3, q = idx & 7;
            CP16(sm + (uint32_t)(AT_KOFF + buf * AT_TILEB + r * AT_ROWB + q * 16),
                 K + (size_t)(kt * 64 + r) * DHD + q * 8);
            CP16(sm + (uint32_t)(AT_VOFF + buf * AT_TILEB + r * AT_ROWB + q * 16),
                 Vt + (size_t)r * SS + kt * 64 + q * 8);
        }
    };

#pragma unroll
    for (int it = 0; it < 4; it++) {
        const int idx = tid + it * 128;
        const int r = idx >> 3, q = idx & 7;
        CP16(sm + (uint32_t)(r * AT_ROWB + q * 16),
             Q + (size_t)(qt * 64 + r) * DHD + q * 8);
    }
    issue_kv(0, 0);
    CPCOMMIT();
    issue_kv(nk > 1 ? 1 : 0, 1);
    CPCOMMIT();

    CPWAIT(1);
    __syncthreads();

    /* Q fragments -> registers */
    uint32_t qf[4][4];
    {
        const __half* Qs = reinterpret_cast<const __half*>(smem);
        const int r = mrow + ar;
#pragma unroll
        for (int k16 = 0; k16 < 4; k16++) {
            const int colb = k16 * 16 + 2 * ac;
            qf[k16][0] = ldh2(Qs + r * AT_PITCH + colb);
            qf[k16][1] = ldh2(Qs + (r + 8) * AT_PITCH + colb);
            qf[k16][2] = ldh2(Qs + r * AT_PITCH + colb + 8);
            qf[k16][3] = ldh2(Qs + (r + 8) * AT_PITCH + colb + 8);
        }
    }

    float m0 = -1e30f, m1 = -1e30f;
    float o[9][4];    /* j=8 accumulates l (ones column) */
#pragma unroll
    for (int j = 0; j < 9; j++)
#pragma unroll
        for (int c = 0; c < 4; c++) o[j][c] = 0.f;

    for (int kt = 0; kt < nk; kt++) {
        CPWAIT(1);
        __syncthreads();
        if (kt + 2 < nk) issue_kv(kt + 2, (kt + 2) % 3);
        CPCOMMIT();

        const int buf = kt % 3;
        const uint32_t kbase = sm + AT_KOFF + buf * AT_TILEB;
        const uint32_t vbase = sm + AT_VOFF + buf * AT_TILEB;

        /* ---- S = Q K^T  (log2 domain: Q pre-scaled) ---- */
        float s[8][4];
#pragma unroll
        for (int j = 0; j < 8; j++)
#pragma unroll
            for (int c = 0; c < 4; c++) s[j][c] = 0.f;

#pragma unroll
        for (int k16 = 0; k16 < 4; k16++) {
            uint32_t kb[8][2];
#pragma unroll
            for (int t = 0; t < 4; t++) {
                uint32_t d0, d1, d2, d3;
                LDSM4(d0, d1, d2, d3, kbase + lm_base[t] + k16 * 32);
                kb[2 * t][0] = d0;     kb[2 * t][1] = d1;
                kb[2 * t + 1][0] = d2; kb[2 * t + 1][1] = d3;
            }
#pragma unroll
            for (int j = 0; j < 8; j++)
                MMA_F16(s[j], qf[k16], kb[j][0], kb[j][1]);
        }

        /* ---- causal mask on diagonal tile ---- */
        const int r0 = mrow + ar, r1 = r0 + 8;
        if (kt == qt) {
#pragma unroll
            for (int j = 0; j < 8; j++) {
                const int c = j * 8 + 2 * ac;
                if (c     > r0) s[j][0] = -1e30f;
                if (c + 1 > r0) s[j][1] = -1e30f;
                if (c     > r1) s[j][2] = -1e30f;
                if (c + 1 > r1) s[j][3] = -1e30f;
            }
        }

        /* ---- online softmax: max + fused f16x2 exp2 ---- */
        float mx0 = -1e30f, mx1 = -1e30f;
#pragma unroll
        for (int j = 0; j < 8; j++) {
            mx0 = fmaxf(mx0, fmaxf(s[j][0], s[j][1]));
            mx1 = fmaxf(mx1, fmaxf(s[j][2], s[j][3]));
        }
        mx0 = fmaxf(mx0, __shfl_xor_sync(0xffffffffu, mx0, 1));
        mx0 = fmaxf(mx0, __shfl_xor_sync(0xffffffffu, mx0, 2));
        mx1 = fmaxf(mx1, __shfl_xor_sync(0xffffffffu, mx1, 1));
        mx1 = fmaxf(mx1, __shfl_xor_sync(0xffffffffu, mx1, 2));

        const float mn0 = fmaxf(m0, mx0), mn1 = fmaxf(m1, mx1);
        const float corr0 = exp2f(m0 - mn0), corr1 = exp2f(m1 - mn1);
        m0 = mn0; m1 = mn1;

        /* P fragments directly as packed fp16 pairs */
        uint32_t pe[8][2];
#pragma unroll
        for (int j = 0; j < 8; j++) {
            pe[j][0] = ex2_h2(s[j][0] - mn0, s[j][1] - mn0);
            pe[j][1] = ex2_h2(s[j][2] - mn1, s[j][3] - mn1);
        }
#pragma unroll
        for (int j = 0; j < 9; j++) {
            o[j][0] *= corr0; o[j][1] *= corr0;
            o[j][2] *= corr1; o[j][3] *= corr1;
        }

        /* ---- O += P V, and l += P·1 via ones-column MMA ---- */
#pragma unroll
        for (int k16 = 0; k16 < 4; k16++) {
            uint32_t pa[4];
            pa[0] = pe[2 * k16][0];
            pa[1] = pe[2 * k16][1];
            pa[2] = pe[2 * k16 + 1][0];
            pa[3] = pe[2 * k16 + 1][1];
            uint32_t vb[8][2];
#pragma unroll
            for (int t = 0; t < 4; t++) {
                uint32_t d0, d1, d2, d3;
                LDSM4(d0, d1, d2, d3, vbase + lm_base[t] + k16 * 32);
                vb[2 * t][0] = d0;     vb[2 * t][1] = d1;
                vb[2 * t + 1][0] = d2; vb[2 * t + 1][1] = d3;
            }
#pragma unroll
            for (int j = 0; j < 8; j++)
                MMA_F16(o[j], pa, vb[j][0], vb[j][1]);
            MMA_F16(o[8], pa, H2_ONES, H2_ONES);
        }
    }

    /* epilogue: l from ones column; normalize; write ctx fp16 [B*S, D] */
    const int b_ = bh >> 4, h = bh & (HH - 1);
    const float inv0 = 1.0f / o[8][0], inv1 = 1.0f / o[8][2];
    const int s0 = qt * 64 + mrow + ar, s1 = s0 + 8;
    __half* p0 = g_ctx + (size_t)(b_ * SS + s0) * DD + h * DHD;
    __half* p1 = g_ctx + (size_t)(b_ * SS + s1) * DD + h * DHD;
#pragma unroll
    for (int j = 0; j < 8; j++) {
        const int c = j * 8 + 2 * ac;
        *reinterpret_cast<__half2*>(&p0[c]) =
            __floats2half2_rn(o[j][0] * inv0, o[j][1] * inv0);
        *reinterpret_cast<__half2*>(&p1[c]) =
            __floats2half2_rn(o[j][2] * inv1, o[j][3] * inv1);
    }
}

/* ------------------------------------------------------------------ */
extern "C" void kernel_launch(void* const* d_in, const int* in_sizes, int n_in,
                              void* d_out, int out_size)
{
    (void)in_sizes; (void)n_in; (void)out_size;
    const float* x  = (const float*)d_in[0];
    const float* Wq = (const float*)d_in[1];
    const float* Wk = (const float*)d_in[2];
    const float* Wv = (const float*)d_in[3];
    const float* Wo = (const float*)d_in[4];
    const float* bo = (const float*)d_in[5];
    float* out = (float*)d_out;

    cudaFuncSetAttribute(qkv_h_kernel,  cudaFuncAttributeMaxDynamicSharedMemorySize, GM_SMEM);
    cudaFuncSetAttribute(out_h_kernel,  cudaFuncAttributeMaxDynamicSharedMemorySize, GM_SMEM);
    cudaFuncSetAttribute(attn_h_kernel, cudaFuncAttributeMaxDynamicSharedMemorySize, AT_SMEM);

    round_x_kernel<<<2048, 256>>>(x);
    wtrans_kernel<<<dim3(32, 32, 4), dim3(32, 8)>>>(Wq, Wk, Wv, Wo);

    dim3 gq(DD / 128, NROWS / 128, 3);
    qkv_h_kernel<<<gq, 256, GM_SMEM>>>();

    dim3 ga(SS / 64, BB * HH);
    attn_h_kernel<<<ga, 128, AT_SMEM>>>();

    dim3 go(DD / 128, NROWS / 128);
    out_h_kernel<<<go, 256, GM_SMEM>>>(bo, out);
}

// round 15
// speedup vs baseline: 1.1406x; 1.1406x over previous
#include <cuda_runtime.h>
#include <cuda_fp16.h>
#include <math.h>
#include <stdint.h>

#define BB 2
#define SS 2048
#define DD 1024
#define HH 16
#define DHD 64
#define NROWS (BB*SS)          /* 4096 */
#define ROPE_LOG2C 0.4152410118609203f   /* log2(10000)/32 */
#define SM_SCALE_LOG2E 0.1803368801111204f  /* 0.125 * log2(e) */

/* Scratch (allocation-free rule) — all fp16 */
__device__ __half g_xh[(size_t)NROWS*DD];
__device__ __half g_wq[DD*DD];     /* transposed, fp16 */
__device__ __half g_wk[DD*DD];
__device__ __half g_wv[DD*DD];
__device__ __half g_wo[DD*DD];
__device__ __half g_q[BB*HH*SS*DHD];       /* [b,h,s,d], pre-scaled by 0.125*log2e */
__device__ __half g_k[BB*HH*SS*DHD];       /* [b,h,s,d] */
__device__ __half g_v[BB*HH*SS*DHD];       /* [b,h,d,s] TRANSPOSED */
__device__ __half g_ctx[(size_t)NROWS*DD]; /* [b*s, d]  */

__device__ __forceinline__ uint32_t smem_u32_of(const void* p) {
    uint32_t a;
    asm("{ .reg .u64 t; cvta.to.shared.u64 t, %1; cvt.u32.u64 %0, t; }" : "=r"(a) : "l"(p));
    return a;
}
__device__ __forceinline__ uint32_t ldh2(const __half* p) {
    return *reinterpret_cast<const uint32_t*>(p);
}
/* pack (lo,hi) to fp16x2 and take exp2 in fp16x2 — one MUFU for two values */
__device__ __forceinline__ uint32_t ex2_h2(float lo, float hi) {
    uint32_t r;
    asm("{\n\t.reg .b32 t;\n\t"
        "cvt.rn.f16x2.f32 t, %2, %1;\n\t"
        "ex2.approx.f16x2 %0, t;\n\t}"
        : "=r"(r) : "f"(lo), "f"(hi));
    return r;
}

#define MMA_F16(c, a, b0, b1) \
    asm volatile("mma.sync.aligned.m16n8k16.row.col.f32.f16.f16.f32 " \
        "{%0,%1,%2,%3}, {%4,%5,%6,%7}, {%8,%9}, {%0,%1,%2,%3};" \
        : "+f"((c)[0]), "+f"((c)[1]), "+f"((c)[2]), "+f"((c)[3]) \
        : "r"((a)[0]), "r"((a)[1]), "r"((a)[2]), "r"((a)[3]), \
          "r"(b0), "r"(b1))

#define LDSM4(d0, d1, d2, d3, addr) \
    asm volatile("ldmatrix.sync.aligned.m8n8.x4.shared.b16 {%0,%1,%2,%3}, [%4];" \
        : "=r"(d0), "=r"(d1), "=r"(d2), "=r"(d3) : "r"(addr))

#define CP16(dst, src) \
    asm volatile("cp.async.cg.shared.global [%0], [%1], 16;" :: "r"(dst), "l"(src))
#define CPCOMMIT() asm volatile("cp.async.commit_group;" ::: "memory")
#define CPWAIT(n)  asm volatile("cp.async.wait_group %0;" :: "n"(n) : "memory")

/* ================================================================== */
/* Pre-pass 1: X -> fp16. 8 floats / thread.                          */
/* ================================================================== */
__global__ void round_x_kernel(const float* __restrict__ X)
{
    const size_t idx = (size_t)(blockIdx.x * 256 + threadIdx.x) * 8;
    float4 v0 = *reinterpret_cast<const float4*>(X + idx);
    float4 v1 = *reinterpret_cast<const float4*>(X + idx + 4);
    __half2* ph = reinterpret_cast<__half2*>(g_xh + idx);
    ph[0] = __floats2half2_rn(v0.x, v0.y);
    ph[1] = __floats2half2_rn(v0.z, v0.w);
    ph[2] = __floats2half2_rn(v1.x, v1.y);
    ph[3] = __floats2half2_rn(v1.z, v1.w);
}

/* ================================================================== */
/* Pre-pass 2: transpose + fp16-convert the 4 weight matrices.        */
/* ================================================================== */
__global__ void wtrans_kernel(const float* __restrict__ Wq,
                              const float* __restrict__ Wk,
                              const float* __restrict__ Wv,
                              const float* __restrict__ Wo)
{
    __shared__ float t[32][33];
    const int z = blockIdx.z;
    const float* src = (z == 0) ? Wq : ((z == 1) ? Wk : ((z == 2) ? Wv : Wo));
    __half* dst = (z == 0) ? g_wq : ((z == 1) ? g_wk : ((z == 2) ? g_wv : g_wo));
    const int r0 = blockIdx.y * 32, c0 = blockIdx.x * 32;
    const int tx = threadIdx.x, ty = threadIdx.y;
#pragma unroll
    for (int k = 0; k < 4; k++)
        t[ty + 8 * k][tx] = src[(size_t)(r0 + ty + 8 * k) * DD + c0 + tx];
    __syncthreads();
#pragma unroll
    for (int k = 0; k < 4; k++)
        dst[(size_t)(c0 + ty + 8 * k) * DD + r0 + tx] = __float2half_rn(t[tx][ty + 8 * k]);
}

/* ================================================================== */
/* GEMM fp16: CTA 128x128, 4 warps (64x64), BK=32, 4-stage, ldmatrix. */
/* ================================================================== */
#define GM_PITCH  40                        /* halves */
#define GM_ROWB   (GM_PITCH*2)              /* 80 bytes */
#define GM_ABYTES (128*GM_ROWB)             /* 10240 */
#define GM_STAGE  (2*GM_ABYTES)             /* 20480 */
#define GM_SMEM   (4 * GM_STAGE)            /* 81920 */

__device__ __forceinline__ void gemm_issue_stage(
    const __half* __restrict__ A, const __half* __restrict__ Wt,
    int row0, int col0, int s, int buf, uint32_t sm)
{
    const int tid = threadIdx.x;
    const uint32_t base = sm + (uint32_t)buf * GM_STAGE;
    const int r = tid >> 2, q = tid & 3;
#pragma unroll
    for (int it = 0; it < 4; it++) {
        const int rr = r + it * 32;
        CP16(base + (uint32_t)(rr * GM_ROWB + q * 16),
             A + (size_t)(row0 + rr) * DD + s * 32 + q * 8);
        CP16(base + GM_ABYTES + (uint32_t)(rr * GM_ROWB + q * 16),
             Wt + (size_t)(col0 + rr) * DD + s * 32 + q * 8);
    }
}

__device__ __forceinline__ void gemm_h(
    const __half* __restrict__ A, const __half* __restrict__ Wt,
    int row0, int col0, uint32_t sm, float acc[4][8][4])
{
    const int lane = threadIdx.x & 31, warp = threadIdx.x >> 5;
    const int wm = warp >> 1, wn = warp & 1;

    /* ldmatrix lane-address components (bytes, tile-relative).
       A-frag (per i, 16 rows x 16 cols): matrices (m,k),(m+8,k),(m,k+8),(m+8,k+8) */
    const uint32_t a_row = (uint32_t)((lane & 7) + ((lane >> 3) & 1) * 8);
    const uint32_t a_col = (uint32_t)(lane >> 4) * 16;            /* bytes */
    uint32_t a_off[4];
#pragma unroll
    for (int i = 0; i < 4; i++)
        a_off[i] = (uint32_t)(wm * 64 + i * 16) * GM_ROWB + a_row * GM_ROWB + a_col;

    /* B-frag (per j-pair): matrices (j0,k),(j0,k+8),(j1,k),(j1,k+8) */
    const uint32_t b_jsel = (uint32_t)(lane >> 4);
    const uint32_t b_ksel = (uint32_t)((lane >> 3) & 1) * 16;
    const uint32_t b_row  = (uint32_t)(lane & 7);
    uint32_t b_off[4];
#pragma unroll
    for (int t = 0; t < 4; t++)
        b_off[t] = GM_ABYTES +
                   (uint32_t)(wn * 64 + (2 * t + b_jsel) * 8 + b_row) * GM_ROWB + b_ksel;

    gemm_issue_stage(A, Wt, row0, col0, 0, 0, sm); CPCOMMIT();
    gemm_issue_stage(A, Wt, row0, col0, 1, 1, sm); CPCOMMIT();
    gemm_issue_stage(A, Wt, row0, col0, 2, 2, sm); CPCOMMIT();

    for (int kt = 0; kt < 32; kt++) {
        CPWAIT(2);
        __syncthreads();
        if (kt + 3 < 32) gemm_issue_stage(A, Wt, row0, col0, kt + 3, (kt + 3) & 3, sm);
        CPCOMMIT();

        const uint32_t stage = sm + (uint32_t)(kt & 3) * GM_STAGE;

#pragma unroll
        for (int k16 = 0; k16 < 2; k16++) {
            const uint32_t kb = (uint32_t)k16 * 32;
            uint32_t a[4][4], b[8][2];
#pragma unroll
            for (int i = 0; i < 4; i++)
                LDSM4(a[i][0], a[i][1], a[i][2], a[i][3], stage + a_off[i] + kb);
#pragma unroll
            for (int t = 0; t < 4; t++) {
                uint32_t d0, d1, d2, d3;
                LDSM4(d0, d1, d2, d3, stage + b_off[t] + kb);
                b[2 * t][0] = d0;     b[2 * t][1] = d1;
                b[2 * t + 1][0] = d2; b[2 * t + 1][1] = d3;
            }
#pragma unroll
            for (int i = 0; i < 4; i++)
#pragma unroll
                for (int j = 0; j < 8; j++)
                    MMA_F16(acc[i][j], a[i], b[j][0], b[j][1]);
        }
    }
}

/* ------------------------------------------------------------------ */
__global__ void __launch_bounds__(128, 2)
qkv_h_kernel()
{
    extern __shared__ __align__(16) char smem[];
    const uint32_t sm = smem_u32_of(smem);
    const int which = blockIdx.z;
    const __half* __restrict__ Wt = (which == 0) ? g_wq : ((which == 1) ? g_wk : g_wv);
    const int row0 = blockIdx.y * 128, col0 = blockIdx.x * 128;

    float acc[4][8][4];
#pragma unroll
    for (int i = 0; i < 4; i++)
#pragma unroll
        for (int j = 0; j < 8; j++)
#pragma unroll
            for (int c = 0; c < 4; c++) acc[i][j][c] = 0.f;

    gemm_h(g_xh, Wt, row0, col0, sm, acc);

    const int lane = threadIdx.x & 31, warp = threadIdx.x >> 5;
    const int wm = warp >> 1, wn = warp & 1;
    const int ar = lane >> 2, ac = lane & 3;
    const int h = (col0 >> 6) + wn;

    if (which < 2) {
        __half* __restrict__ dst = (which == 0) ? g_q : g_k;
        const float post = (which == 0) ? SM_SCALE_LOG2E : 1.0f;
        /* this thread's 8 rows are base + 8t (same batch, consecutive s) */
        const int rowb = row0 + wm * 64 + ar;
        const int b_ = rowb >> 11, sbase = rowb & (SS - 1);
        __half* dhead = dst + ((size_t)(b_ * HH + h) * SS) * DHD;
#pragma unroll
        for (int j = 0; j < 8; j++) {
            const float freq = exp2f(-(float)(j * 4 + ac) * ROPE_LOG2C);
            const int dh = j * 8 + 2 * ac;
            float sn, cs, sd, cd;
            sincosf((float)sbase * freq, &sn, &cs);
            sincosf(8.0f * freq, &sd, &cd);
#pragma unroll
            for (int t = 0; t < 8; t++) {
                const int i = t >> 1, half_ = t & 1;
                const float e = acc[i][j][half_ * 2], o = acc[i][j][half_ * 2 + 1];
                __half* drow = dhead + (size_t)(sbase + 8 * t) * DHD;
                *reinterpret_cast<__half2*>(&drow[dh]) =
                    __floats2half2_rn((e * cs - o * sn) * post,
                                      (e * sn + o * cs) * post);
                const float csn = cs * cd - sn * sd;
                sn = sn * cd + cs * sd;
                cs = csn;
            }
        }
    } else {
        /* V: store TRANSPOSED [b,h,d,s] */
#pragma unroll
        for (int i = 0; i < 4; i++) {
#pragma unroll
            for (int half_ = 0; half_ < 2; half_++) {
                const int row = row0 + wm * 64 + i * 16 + ar + half_ * 8;
                const int b_ = row >> 11, s = row & (SS - 1);
                __half* dbase = g_v + ((size_t)(b_ * HH + h)) * DHD * SS;
#pragma unroll
                for (int j = 0; j < 8; j++) {
                    const int dh = j * 8 + 2 * ac;
                    dbase[(size_t)dh * SS + s]       = __float2half_rn(acc[i][j][half_ * 2]);
                    dbase[(size_t)(dh + 1) * SS + s] = __float2half_rn(acc[i][j][half_ * 2 + 1]);
                }
            }
        }
    }
}

/* ------------------------------------------------------------------ */
__global__ void __launch_bounds__(128, 2)
out_h_kernel(const float* __restrict__ bo, float* __restrict__ out)
{
    extern __shared__ __align__(16) char smem[];
    const uint32_t sm = smem_u32_of(smem);
    const int row0 = blockIdx.y * 128, col0 = blockIdx.x * 128;

    float acc[4][8][4];
#pragma unroll
    for (int i = 0; i < 4; i++)
#pragma unroll
        for (int j = 0; j < 8; j++)
#pragma unroll
            for (int c = 0; c < 4; c++) acc[i][j][c] = 0.f;

    gemm_h(g_ctx, g_wo, row0, col0, sm, acc);

    const int lane = threadIdx.x & 31, warp = threadIdx.x >> 5;
    const int wm = warp >> 1, wn = warp & 1;
    const int ar = lane >> 2, ac = lane & 3;

#pragma unroll
    for (int i = 0; i < 4; i++) {
        const int r = row0 + wm * 64 + i * 16 + ar;
#pragma unroll
        for (int j = 0; j < 8; j++) {
            const int col = col0 + wn * 64 + j * 8 + 2 * ac;
            const float bx = bo[col], by = bo[col + 1];
            *reinterpret_cast<float2*>(&out[(size_t)r * DD + col]) =
                make_float2(acc[i][j][0] + bx, acc[i][j][1] + by);
            *reinterpret_cast<float2*>(&out[(size_t)(r + 8) * DD + col]) =
                make_float2(acc[i][j][2] + bx, acc[i][j][3] + by);
        }
    }
}

/* ================================================================== */
/* Flash attention fp16 v5 (R13, unchanged): ldmatrix K/V frags;      */
/* P via fused f16x2 ex2; l via ones-column MMA; 3-buffer KV ring.    */
/* ================================================================== */
#define AT_PITCH  72                         /* halves */
#define AT_ROWB   (AT_PITCH*2)               /* 144 B */
#define AT_TILEB  (64*AT_ROWB)               /* 9216 */
#define AT_KOFF   AT_TILEB
#define AT_VOFF   (4*AT_TILEB)
#define AT_SMEM   (7*AT_TILEB)               /* 64512 */
#define H2_ONES   0x3C003C00u

__global__ void __launch_bounds__(128, 3)
attn_h_kernel()
{
    extern __shared__ __align__(16) char smem[];
    const uint32_t sm = smem_u32_of(smem);
    const int bh = blockIdx.y;
    const int qt = gridDim.x - 1 - blockIdx.x;   /* heavy-first */
    const __half* __restrict__ Q  = g_q + (size_t)bh * SS * DHD;
    const __half* __restrict__ K  = g_k + (size_t)bh * SS * DHD;
    const __half* __restrict__ Vt = g_v + (size_t)bh * DHD * SS;  /* [d][s] */

    const int tid = threadIdx.x;
    const int lane = tid & 31, warp = tid >> 5;
    const int ar = lane >> 2, ac = lane & 3;
    const int nk = qt + 1;
    const int mrow = warp * 16;

    const uint32_t lnrow = (uint32_t)(lane & 7);
    const uint32_t jsel  = (uint32_t)(lane >> 4);
    const uint32_t ksel  = (uint32_t)((lane >> 3) & 1) * 16;
    uint32_t lm_base[4];
#pragma unroll
    for (int t = 0; t < 4; t++)
        lm_base[t] = ((2 * t + jsel) * 8 + lnrow) * AT_ROWB + ksel;

    auto issue_kv = [&](int kt, int buf) {
#pragma unroll
        for (int it = 0; it < 4; it++) {
            const int idx = tid + it * 128;
            const int r = idx >> 3, q = idx & 7;
            CP16(sm + (uint32_t)(AT_KOFF + buf * AT_TILEB + r * AT_ROWB + q * 16),
                 K + (size_t)(kt * 64 + r) * DHD + q * 8);
            CP16(sm + (uint32_t)(AT_VOFF + buf * AT_TILEB + r * AT_ROWB + q * 16),
                 Vt + (size_t)r * SS + kt * 64 + q * 8);
        }
    };

#pragma unroll
    for (int it = 0; it < 4; it++) {
        const int idx = tid + it * 128;
        const int r = idx >> 3, q = idx & 7;
        CP16(sm + (uint32_t)(r * AT_ROWB + q * 16),
             Q + (size_t)(qt * 64 + r) * DHD + q * 8);
    }
    issue_kv(0, 0);
    CPCOMMIT();
    issue_kv(nk > 1 ? 1 : 0, 1);
    CPCOMMIT();

    CPWAIT(1);
    __syncthreads();

    /* Q fragments -> registers */
    uint32_t qf[4][4];
    {
        const __half* Qs = reinterpret_cast<const __half*>(smem);
        const int r = mrow + ar;
#pragma unroll
        for (int k16 = 0; k16 < 4; k16++) {
            const int colb = k16 * 16 + 2 * ac;
            qf[k16][0] = ldh2(Qs + r * AT_PITCH + colb);
            qf[k16][1] = ldh2(Qs + (r + 8) * AT_PITCH + colb);
            qf[k16][2] = ldh2(Qs + r * AT_PITCH + colb + 8);
            qf[k16][3] = ldh2(Qs + (r + 8) * AT_PITCH + colb + 8);
        }
    }

    float m0 = -1e30f, m1 = -1e30f;
    float o[9][4];    /* j=8 accumulates l (ones column) */
#pragma unroll
    for (int j = 0; j < 9; j++)
#pragma unroll
        for (int c = 0; c < 4; c++) o[j][c] = 0.f;

    for (int kt = 0; kt < nk; kt++) {
        CPWAIT(1);
        __syncthreads();
        if (kt + 2 < nk) issue_kv(kt + 2, (kt + 2) % 3);
        CPCOMMIT();

        const int buf = kt % 3;
        const uint32_t kbase = sm + AT_KOFF + buf * AT_TILEB;
        const uint32_t vbase = sm + AT_VOFF + buf * AT_TILEB;

        /* ---- S = Q K^T  (log2 domain: Q pre-scaled) ---- */
        float s[8][4];
#pragma unroll
        for (int j = 0; j < 8; j++)
#pragma unroll
            for (int c = 0; c < 4; c++) s[j][c] = 0.f;

#pragma unroll
        for (int k16 = 0; k16 < 4; k16++) {
            uint32_t kb[8][2];
#pragma unroll
            for (int t = 0; t < 4; t++) {
                uint32_t d0, d1, d2, d3;
                LDSM4(d0, d1, d2, d3, kbase + lm_base[t] + k16 * 32);
                kb[2 * t][0] = d0;     kb[2 * t][1] = d1;
                kb[2 * t + 1][0] = d2; kb[2 * t + 1][1] = d3;
            }
#pragma unroll
            for (int j = 0; j < 8; j++)
                MMA_F16(s[j], qf[k16], kb[j][0], kb[j][1]);
        }

        /* ---- causal mask on diagonal tile ---- */
        const int r0 = mrow + ar, r1 = r0 + 8;
        if (kt == qt) {
#pragma unroll
            for (int j = 0; j < 8; j++) {
                const int c = j * 8 + 2 * ac;
                if (c     > r0) s[j][0] = -1e30f;
                if (c + 1 > r0) s[j][1] = -1e30f;
                if (c     > r1) s[j][2] = -1e30f;
                if (c + 1 > r1) s[j][3] = -1e30f;
            }
        }

        /* ---- online softmax: max + fused f16x2 exp2 ---- */
        float mx0 = -1e30f, mx1 = -1e30f;
#pragma unroll
        for (int j = 0; j < 8; j++) {
            mx0 = fmaxf(mx0, fmaxf(s[j][0], s[j][1]));
            mx1 = fmaxf(mx1, fmaxf(s[j][2], s[j][3]));
        }
        mx0 = fmaxf(mx0, __shfl_xor_sync(0xffffffffu, mx0, 1));
        mx0 = fmaxf(mx0, __shfl_xor_sync(0xffffffffu, mx0, 2));
        mx1 = fmaxf(mx1, __shfl_xor_sync(0xffffffffu, mx1, 1));
        mx1 = fmaxf(mx1, __shfl_xor_sync(0xffffffffu, mx1, 2));

        const float mn0 = fmaxf(m0, mx0), mn1 = fmaxf(m1, mx1);
        const float corr0 = exp2f(m0 - mn0), corr1 = exp2f(m1 - mn1);
        m0 = mn0; m1 = mn1;

        /* P fragments directly as packed fp16 pairs */
        uint32_t pe[8][2];
#pragma unroll
        for (int j = 0; j < 8; j++) {
            pe[j][0] = ex2_h2(s[j][0] - mn0, s[j][1] - mn0);
            pe[j][1] = ex2_h2(s[j][2] - mn1, s[j][3] - mn1);
        }
#pragma unroll
        for (int j = 0; j < 9; j++) {
            o[j][0] *= corr0; o[j][1] *= corr0;
            o[j][2] *= corr1; o[j][3] *= corr1;
        }

        /* ---- O += P V, and l += P·1 via ones-column MMA ---- */
#pragma unroll
        for (int k16 = 0; k16 < 4; k16++) {
            uint32_t pa[4];
            pa[0] = pe[2 * k16][0];
            pa[1] = pe[2 * k16][1];
            pa[2] = pe[2 * k16 + 1][0];
            pa[3] = pe[2 * k16 + 1][1];
            uint32_t vb[8][2];
#pragma unroll
            for (int t = 0; t < 4; t++) {
                uint32_t d0, d1, d2, d3;
                LDSM4(d0, d1, d2, d3, vbase + lm_base[t] + k16 * 32);
                vb[2 * t][0] = d0;     vb[2 * t][1] = d1;
                vb[2 * t + 1][0] = d2; vb[2 * t + 1][1] = d3;
            }
#pragma unroll
            for (int j = 0; j < 8; j++)
                MMA_F16(o[j], pa, vb[j][0], vb[j][1]);
            MMA_F16(o[8], pa, H2_ONES, H2_ONES);
        }
    }

    /* epilogue: l from ones column; normalize; write ctx fp16 [B*S, D] */
    const int b_ = bh >> 4, h = bh & (HH - 1);
    const float inv0 = 1.0f / o[8][0], inv1 = 1.0f / o[8][2];
    const int s0 = qt * 64 + mrow + ar, s1 = s0 + 8;
    __half* p0 = g_ctx + (size_t)(b_ * SS + s0) * DD + h * DHD;
    __half* p1 = g_ctx + (size_t)(b_ * SS + s1) * DD + h * DHD;
#pragma unroll
    for (int j = 0; j < 8; j++) {
        const int c = j * 8 + 2 * ac;
        *reinterpret_cast<__half2*>(&p0[c]) =
            __floats2half2_rn(o[j][0] * inv0, o[j][1] * inv0);
        *reinterpret_cast<__half2*>(&p1[c]) =
            __floats2half2_rn(o[j][2] * inv1, o[j][3] * inv1);
    }
}

/* ------------------------------------------------------------------ */
extern "C" void kernel_launch(void* const* d_in, const int* in_sizes, int n_in,
                              void* d_out, int out_size)
{
    (void)in_sizes; (void)n_in; (void)out_size;
    const float* x  = (const float*)d_in[0];
    const float* Wq = (const float*)d_in[1];
    const float* Wk = (const float*)d_in[2];
    const float* Wv = (const float*)d_in[3];
    const float* Wo = (const float*)d_in[4];
    const float* bo = (const float*)d_in[5];
    float* out = (float*)d_out;

    cudaFuncSetAttribute(qkv_h_kernel,  cudaFuncAttributeMaxDynamicSharedMemorySize, GM_SMEM);
    cudaFuncSetAttribute(out_h_kernel,  cudaFuncAttributeMaxDynamicSharedMemorySize, GM_SMEM);
    cudaFuncSetAttribute(attn_h_kernel, cudaFuncAttributeMaxDynamicSharedMemorySize, AT_SMEM);

    round_x_kernel<<<2048, 256>>>(x);
    wtrans_kernel<<<dim3(32, 32, 4), dim3(32, 8)>>>(Wq, Wk, Wv, Wo);

    dim3 gq(DD / 128, NROWS / 128, 3);
    qkv_h_kernel<<<gq, 128, GM_SMEM>>>();

    dim3 ga(SS / 64, BB * HH);
    attn_h_kernel<<<ga, 128, AT_SMEM>>>();

    dim3 go(DD / 128, NROWS / 128);
    out_h_kernel<<<go, 128, GM_SMEM>>>(bo, out);
}

// round 16
// speedup vs baseline: 1.1481x; 1.0066x over previous
#include <cuda_runtime.h>
#include <cuda_fp16.h>
#include <math.h>
#include <stdint.h>

#define BB 2
#define SS 2048
#define DD 1024
#define HH 16
#define DHD 64
#define NROWS (BB*SS)          /* 4096 */
#define ROPE_LOG2C 0.4152410118609203f   /* log2(10000)/32 */
#define SM_SCALE_LOG2E 0.1803368801111204f  /* 0.125 * log2(e) */

/* Scratch (allocation-free rule) — all fp16 */
__device__ __half g_xh[(size_t)NROWS*DD];
__device__ __half g_wq[DD*DD];     /* transposed, fp16 */
__device__ __half g_wk[DD*DD];
__device__ __half g_wv[DD*DD];
__device__ __half g_wo[DD*DD];
__device__ __half g_q[BB*HH*SS*DHD];       /* [b,h,s,d], pre-scaled by 0.125*log2e */
__device__ __half g_k[BB*HH*SS*DHD];       /* [b,h,s,d] */
__device__ __half g_v[BB*HH*SS*DHD];       /* [b,h,s,d] */
__device__ __half g_ctx[(size_t)NROWS*DD]; /* [b*s, d]  */

__device__ __forceinline__ uint32_t smem_u32_of(const void* p) {
    uint32_t a;
    asm("{ .reg .u64 t; cvta.to.shared.u64 t, %1; cvt.u32.u64 %0, t; }" : "=r"(a) : "l"(p));
    return a;
}
__device__ __forceinline__ uint32_t ldh2(const __half* p) {
    return *reinterpret_cast<const uint32_t*>(p);
}
/* pack (lo,hi) to fp16x2 and take exp2 in fp16x2 — one MUFU for two values */
__device__ __forceinline__ uint32_t ex2_h2(float lo, float hi) {
    uint32_t r;
    asm("{\n\t.reg .b32 t;\n\t"
        "cvt.rn.f16x2.f32 t, %2, %1;\n\t"
        "ex2.approx.f16x2 %0, t;\n\t}"
        : "=r"(r) : "f"(lo), "f"(hi));
    return r;
}

#define MMA_F16(c, a, b0, b1) \
    asm volatile("mma.sync.aligned.m16n8k16.row.col.f32.f16.f16.f32 " \
        "{%0,%1,%2,%3}, {%4,%5,%6,%7}, {%8,%9}, {%0,%1,%2,%3};" \
        : "+f"((c)[0]), "+f"((c)[1]), "+f"((c)[2]), "+f"((c)[3]) \
        : "r"((a)[0]), "r"((a)[1]), "r"((a)[2]), "r"((a)[3]), \
          "r"(b0), "r"(b1))

#define LDSM4(d0, d1, d2, d3, addr) \
    asm volatile("ldmatrix.sync.aligned.m8n8.x4.shared.b16 {%0,%1,%2,%3}, [%4];" \
        : "=r"(d0), "=r"(d1), "=r"(d2), "=r"(d3) : "r"(addr))

#define LDSM4T(d0, d1, d2, d3, addr) \
    asm volatile("ldmatrix.sync.aligned.m8n8.x4.trans.shared.b16 {%0,%1,%2,%3}, [%4];" \
        : "=r"(d0), "=r"(d1), "=r"(d2), "=r"(d3) : "r"(addr))

#define CP16(dst, src) \
    asm volatile("cp.async.cg.shared.global [%0], [%1], 16;" :: "r"(dst), "l"(src))
#define CPCOMMIT() asm volatile("cp.async.commit_group;" ::: "memory")
#define CPWAIT(n)  asm volatile("cp.async.wait_group %0;" :: "n"(n) : "memory")

/* ================================================================== */
/* Pre-pass 1: X -> fp16. 8 floats / thread.                          */
/* ================================================================== */
__global__ void round_x_kernel(const float* __restrict__ X)
{
    const size_t idx = (size_t)(blockIdx.x * 256 + threadIdx.x) * 8;
    float4 v0 = *reinterpret_cast<const float4*>(X + idx);
    float4 v1 = *reinterpret_cast<const float4*>(X + idx + 4);
    __half2* ph = reinterpret_cast<__half2*>(g_xh + idx);
    ph[0] = __floats2half2_rn(v0.x, v0.y);
    ph[1] = __floats2half2_rn(v0.z, v0.w);
    ph[2] = __floats2half2_rn(v1.x, v1.y);
    ph[3] = __floats2half2_rn(v1.z, v1.w);
}

/* ================================================================== */
/* Pre-pass 2: transpose + fp16-convert the 4 weight matrices.        */
/* ================================================================== */
__global__ void wtrans_kernel(const float* __restrict__ Wq,
                              const float* __restrict__ Wk,
                              const float* __restrict__ Wv,
                              const float* __restrict__ Wo)
{
    __shared__ float t[32][33];
    const int z = blockIdx.z;
    const float* src = (z == 0) ? Wq : ((z == 1) ? Wk : ((z == 2) ? Wv : Wo));
    __half* dst = (z == 0) ? g_wq : ((z == 1) ? g_wk : ((z == 2) ? g_wv : g_wo));
    const int r0 = blockIdx.y * 32, c0 = blockIdx.x * 32;
    const int tx = threadIdx.x, ty = threadIdx.y;
#pragma unroll
    for (int k = 0; k < 4; k++)
        t[ty + 8 * k][tx] = src[(size_t)(r0 + ty + 8 * k) * DD + c0 + tx];
    __syncthreads();
#pragma unroll
    for (int k = 0; k < 4; k++)
        dst[(size_t)(c0 + ty + 8 * k) * DD + r0 + tx] = __float2half_rn(t[tx][ty + 8 * k]);
}

/* ================================================================== */
/* GEMM fp16: CTA 128x128, 4 warps (64x64), BK=32, 4-stage, ldmatrix. */
/* ================================================================== */
#define GM_PITCH  40                        /* halves */
#define GM_ROWB   (GM_PITCH*2)              /* 80 bytes */
#define GM_ABYTES (128*GM_ROWB)             /* 10240 */
#define GM_STAGE  (2*GM_ABYTES)             /* 20480 */
#define GM_SMEM   (4 * GM_STAGE)            /* 81920 */

__device__ __forceinline__ void gemm_issue_stage(
    const __half* __restrict__ A, const __half* __restrict__ Wt,
    int row0, int col0, int s, int buf, uint32_t sm)
{
    const int tid = threadIdx.x;
    const uint32_t base = sm + (uint32_t)buf * GM_STAGE;
    const int r = tid >> 2, q = tid & 3;
#pragma unroll
    for (int it = 0; it < 4; it++) {
        const int rr = r + it * 32;
        CP16(base + (uint32_t)(rr * GM_ROWB + q * 16),
             A + (size_t)(row0 + rr) * DD + s * 32 + q * 8);
        CP16(base + GM_ABYTES + (uint32_t)(rr * GM_ROWB + q * 16),
             Wt + (size_t)(col0 + rr) * DD + s * 32 + q * 8);
    }
}

__device__ __forceinline__ void gemm_h(
    const __half* __restrict__ A, const __half* __restrict__ Wt,
    int row0, int col0, uint32_t sm, float acc[4][8][4])
{
    const int lane = threadIdx.x & 31, warp = threadIdx.x >> 5;
    const int wm = warp >> 1, wn = warp & 1;

    const uint32_t a_row = (uint32_t)((lane & 7) + ((lane >> 3) & 1) * 8);
    const uint32_t a_col = (uint32_t)(lane >> 4) * 16;            /* bytes */
    uint32_t a_off[4];
#pragma unroll
    for (int i = 0; i < 4; i++)
        a_off[i] = (uint32_t)(wm * 64 + i * 16) * GM_ROWB + a_row * GM_ROWB + a_col;

    const uint32_t b_jsel = (uint32_t)(lane >> 4);
    const uint32_t b_ksel = (uint32_t)((lane >> 3) & 1) * 16;
    const uint32_t b_row  = (uint32_t)(lane & 7);
    uint32_t b_off[4];
#pragma unroll
    for (int t = 0; t < 4; t++)
        b_off[t] = GM_ABYTES +
                   (uint32_t)(wn * 64 + (2 * t + b_jsel) * 8 + b_row) * GM_ROWB + b_ksel;

    gemm_issue_stage(A, Wt, row0, col0, 0, 0, sm); CPCOMMIT();
    gemm_issue_stage(A, Wt, row0, col0, 1, 1, sm); CPCOMMIT();
    gemm_issue_stage(A, Wt, row0, col0, 2, 2, sm); CPCOMMIT();

    for (int kt = 0; kt < 32; kt++) {
        CPWAIT(2);
        __syncthreads();
        if (kt + 3 < 32) gemm_issue_stage(A, Wt, row0, col0, kt + 3, (kt + 3) & 3, sm);
        CPCOMMIT();

        const uint32_t stage = sm + (uint32_t)(kt & 3) * GM_STAGE;

#pragma unroll
        for (int k16 = 0; k16 < 2; k16++) {
            const uint32_t kb = (uint32_t)k16 * 32;
            uint32_t a[4][4], b[8][2];
#pragma unroll
            for (int i = 0; i < 4; i++)
                LDSM4(a[i][0], a[i][1], a[i][2], a[i][3], stage + a_off[i] + kb);
#pragma unroll
            for (int t = 0; t < 4; t++) {
                uint32_t d0, d1, d2, d3;
                LDSM4(d0, d1, d2, d3, stage + b_off[t] + kb);
                b[2 * t][0] = d0;     b[2 * t][1] = d1;
                b[2 * t + 1][0] = d2; b[2 * t + 1][1] = d3;
            }
#pragma unroll
            for (int i = 0; i < 4; i++)
#pragma unroll
                for (int j = 0; j < 8; j++)
                    MMA_F16(acc[i][j], a[i], b[j][0], b[j][1]);
        }
    }
}

/* ------------------------------------------------------------------ */
__global__ void __launch_bounds__(128, 2)
qkv_h_kernel()
{
    extern __shared__ __align__(16) char smem[];
    const uint32_t sm = smem_u32_of(smem);
    const int which = blockIdx.z;
    const __half* __restrict__ Wt = (which == 0) ? g_wq : ((which == 1) ? g_wk : g_wv);
    const int row0 = blockIdx.y * 128, col0 = blockIdx.x * 128;

    float acc[4][8][4];
#pragma unroll
    for (int i = 0; i < 4; i++)
#pragma unroll
        for (int j = 0; j < 8; j++)
#pragma unroll
            for (int c = 0; c < 4; c++) acc[i][j][c] = 0.f;

    gemm_h(g_xh, Wt, row0, col0, sm, acc);

    const int lane = threadIdx.x & 31, warp = threadIdx.x >> 5;
    const int wm = warp >> 1, wn = warp & 1;
    const int ar = lane >> 2, ac = lane & 3;
    const int h = (col0 >> 6) + wn;

    if (which < 2) {
        __half* __restrict__ dst = (which == 0) ? g_q : g_k;
        const float post = (which == 0) ? SM_SCALE_LOG2E : 1.0f;
        /* this thread's 8 rows are base + 8t (same batch, consecutive s) */
        const int rowb = row0 + wm * 64 + ar;
        const int b_ = rowb >> 11, sbase = rowb & (SS - 1);
        __half* dhead = dst + ((size_t)(b_ * HH + h) * SS) * DHD;
#pragma unroll
        for (int j = 0; j < 8; j++) {
            const float freq = exp2f(-(float)(j * 4 + ac) * ROPE_LOG2C);
            const int dh = j * 8 + 2 * ac;
            float sn, cs, sd, cd;
            sincosf((float)sbase * freq, &sn, &cs);
            sincosf(8.0f * freq, &sd, &cd);
#pragma unroll
            for (int t = 0; t < 8; t++) {
                const int i = t >> 1, half_ = t & 1;
                const float e = acc[i][j][half_ * 2], o = acc[i][j][half_ * 2 + 1];
                __half* drow = dhead + (size_t)(sbase + 8 * t) * DHD;
                *reinterpret_cast<__half2*>(&drow[dh]) =
                    __floats2half2_rn((e * cs - o * sn) * post,
                                      (e * sn + o * cs) * post);
                const float csn = cs * cd - sn * sd;
                sn = sn * cd + cs * sd;
                cs = csn;
            }
        }
    } else {
        /* V: row store [b,h,s,d] — coalesced half2 writes */
#pragma unroll
        for (int i = 0; i < 4; i++) {
#pragma unroll
            for (int half_ = 0; half_ < 2; half_++) {
                const int row = row0 + wm * 64 + i * 16 + ar + half_ * 8;
                const int b_ = row >> 11, s = row & (SS - 1);
                __half* drow = g_v + ((size_t)(b_ * HH + h) * SS + s) * DHD;
#pragma unroll
                for (int j = 0; j < 8; j++) {
                    const int dh = j * 8 + 2 * ac;
                    *reinterpret_cast<__half2*>(&drow[dh]) =
                        __floats2half2_rn(acc[i][j][half_ * 2], acc[i][j][half_ * 2 + 1]);
                }
            }
        }
    }
}

/* ------------------------------------------------------------------ */
__global__ void __launch_bounds__(128, 2)
out_h_kernel(const float* __restrict__ bo, float* __restrict__ out)
{
    extern __shared__ __align__(16) char smem[];
    const uint32_t sm = smem_u32_of(smem);
    const int row0 = blockIdx.y * 128, col0 = blockIdx.x * 128;

    float acc[4][8][4];
#pragma unroll
    for (int i = 0; i < 4; i++)
#pragma unroll
        for (int j = 0; j < 8; j++)
#pragma unroll
            for (int c = 0; c < 4; c++) acc[i][j][c] = 0.f;

    gemm_h(g_ctx, g_wo, row0, col0, sm, acc);

    const int lane = threadIdx.x & 31, warp = threadIdx.x >> 5;
    const int wm = warp >> 1, wn = warp & 1;
    const int ar = lane >> 2, ac = lane & 3;

#pragma unroll
    for (int i = 0; i < 4; i++) {
        const int r = row0 + wm * 64 + i * 16 + ar;
#pragma unroll
        for (int j = 0; j < 8; j++) {
            const int col = col0 + wn * 64 + j * 8 + 2 * ac;
            const float bx = bo[col], by = bo[col + 1];
            *reinterpret_cast<float2*>(&out[(size_t)r * DD + col]) =
                make_float2(acc[i][j][0] + bx, acc[i][j][1] + by);
            *reinterpret_cast<float2*>(&out[(size_t)(r + 8) * DD + col]) =
                make_float2(acc[i][j][2] + bx, acc[i][j][3] + by);
        }
    }
}

/* ================================================================== */
/* Flash attention fp16 v6: K via ldmatrix, V via ldmatrix.trans      */
/* (V stored [b,h,s,d]); Q frags via ldmatrix; P via fused f16x2 ex2; */
/* l via ones-column MMA; 3-buffer KV ring (1 sync/tile).             */
/* ================================================================== */
#define AT_PITCH  72                         /* halves */
#define AT_ROWB   (AT_PITCH*2)               /* 144 B */
#define AT_TILEB  (64*AT_ROWB)               /* 9216 */
#define AT_KOFF   AT_TILEB
#define AT_VOFF   (4*AT_TILEB)
#define AT_SMEM   (7*AT_TILEB)               /* 64512 */
#define H2_ONES   0x3C003C00u

__global__ void __launch_bounds__(128, 3)
attn_h_kernel()
{
    extern __shared__ __align__(16) char smem[];
    const uint32_t sm = smem_u32_of(smem);
    const int bh = blockIdx.y;
    const int qt = gridDim.x - 1 - blockIdx.x;   /* heavy-first */
    const __half* __restrict__ Q = g_q + (size_t)bh * SS * DHD;
    const __half* __restrict__ K = g_k + (size_t)bh * SS * DHD;
    const __half* __restrict__ V = g_v + (size_t)bh * SS * DHD;

    const int tid = threadIdx.x;
    const int lane = tid & 31, warp = tid >> 5;
    const int ar = lane >> 2, ac = lane & 3;
    const int nk = qt + 1;
    const int mrow = warp * 16;

    /* K-frag (non-trans): matrices (j0,k0),(j0,k8),(j1,k0),(j1,k8) */
    const uint32_t lnrow = (uint32_t)(lane & 7);
    const uint32_t jsel  = (uint32_t)(lane >> 4);
    const uint32_t ksel  = (uint32_t)((lane >> 3) & 1) * 16;
    uint32_t lm_base[4];
#pragma unroll
    for (int t = 0; t < 4; t++)
        lm_base[t] = ((2 * t + jsel) * 8 + lnrow) * AT_ROWB + ksel;

    /* V-frag (trans, V stored [s][d]): matrices (k0,j0),(k8,j0),(k0,j1),(k8,j1);
       row = k16*16 + kblk*8 + lnrow, col byte = (2t+jsel)*16 */
    const uint32_t v_kblk = (uint32_t)((lane >> 3) & 1) * 8;
    uint32_t vm_base[4];
#pragma unroll
    for (int t = 0; t < 4; t++)
        vm_base[t] = (v_kblk + lnrow) * AT_ROWB + (2 * t + jsel) * 16;

    auto issue_kv = [&](int kt, int buf) {
#pragma unroll
        for (int it = 0; it < 4; it++) {
            const int idx = tid + it * 128;
            const int r = idx >> 3, q = idx & 7;
            CP16(sm + (uint32_t)(AT_KOFF + buf * AT_TILEB + r * AT_ROWB + q * 16),
                 K + (size_t)(kt * 64 + r) * DHD + q * 8);
            CP16(sm + (uint32_t)(AT_VOFF + buf * AT_TILEB + r * AT_ROWB + q * 16),
                 V + (size_t)(kt * 64 + r) * DHD + q * 8);
        }
    };

#pragma unroll
    for (int it = 0; it < 4; it++) {
        const int idx = tid + it * 128;
        const int r = idx >> 3, q = idx & 7;
        CP16(sm + (uint32_t)(r * AT_ROWB + q * 16),
             Q + (size_t)(qt * 64 + r) * DHD + q * 8);
    }
    issue_kv(0, 0);
    CPCOMMIT();
    issue_kv(nk > 1 ? 1 : 0, 1);
    CPCOMMIT();

    CPWAIT(1);
    __syncthreads();

    /* Q fragments -> registers via ldmatrix.x4 */
    uint32_t qf[4][4];
    {
        const uint32_t q_addr = sm +
            (uint32_t)(mrow + (lane & 7) + ((lane >> 3) & 1) * 8) * AT_ROWB +
            (uint32_t)(lane >> 4) * 16;
#pragma unroll
        for (int k16 = 0; k16 < 4; k16++)
            LDSM4(qf[k16][0], qf[k16][1], qf[k16][2], qf[k16][3], q_addr + k16 * 32);
    }

    float m0 = -1e30f, m1 = -1e30f;
    float o[9][4];    /* j=8 accumulates l (ones column) */
#pragma unroll
    for (int j = 0; j < 9; j++)
#pragma unroll
        for (int c = 0; c < 4; c++) o[j][c] = 0.f;

    for (int kt = 0; kt < nk; kt++) {
        CPWAIT(1);
        __syncthreads();
        if (kt + 2 < nk) issue_kv(kt + 2, (kt + 2) % 3);
        CPCOMMIT();

        const int buf = kt % 3;
        const uint32_t kbase = sm + AT_KOFF + buf * AT_TILEB;
        const uint32_t vbase = sm + AT_VOFF + buf * AT_TILEB;

        /* ---- S = Q K^T  (log2 domain: Q pre-scaled) ---- */
        float s[8][4];
#pragma unroll
        for (int j = 0; j < 8; j++)
#pragma unroll
            for (int c = 0; c < 4; c++) s[j][c] = 0.f;

#pragma unroll
        for (int k16 = 0; k16 < 4; k16++) {
            uint32_t kb[8][2];
#pragma unroll
            for (int t = 0; t < 4; t++) {
                uint32_t d0, d1, d2, d3;
                LDSM4(d0, d1, d2, d3, kbase + lm_base[t] + k16 * 32);
                kb[2 * t][0] = d0;     kb[2 * t][1] = d1;
                kb[2 * t + 1][0] = d2; kb[2 * t + 1][1] = d3;
            }
#pragma unroll
            for (int j = 0; j < 8; j++)
                MMA_F16(s[j], qf[k16], kb[j][0], kb[j][1]);
        }

        /* ---- causal mask on diagonal tile ---- */
        const int r0 = mrow + ar, r1 = r0 + 8;
        if (kt == qt) {
#pragma unroll
            for (int j = 0; j < 8; j++) {
                const int c = j * 8 + 2 * ac;
                if (c     > r0) s[j][0] = -1e30f;
                if (c + 1 > r0) s[j][1] = -1e30f;
                if (c     > r1) s[j][2] = -1e30f;
                if (c + 1 > r1) s[j][3] = -1e30f;
            }
        }

        /* ---- online softmax: max + fused f16x2 exp2 ---- */
        float mx0 = -1e30f, mx1 = -1e30f;
#pragma unroll
        for (int j = 0; j < 8; j++) {
            mx0 = fmaxf(mx0, fmaxf(s[j][0], s[j][1]));
            mx1 = fmaxf(mx1, fmaxf(s[j][2], s[j][3]));
        }
        mx0 = fmaxf(mx0, __shfl_xor_sync(0xffffffffu, mx0, 1));
        mx0 = fmaxf(mx0, __shfl_xor_sync(0xffffffffu, mx0, 2));
        mx1 = fmaxf(mx1, __shfl_xor_sync(0xffffffffu, mx1, 1));
        mx1 = fmaxf(mx1, __shfl_xor_sync(0xffffffffu, mx1, 2));

        const float mn0 = fmaxf(m0, mx0), mn1 = fmaxf(m1, mx1);
        const float corr0 = exp2f(m0 - mn0), corr1 = exp2f(m1 - mn1);
        m0 = mn0; m1 = mn1;

        /* P fragments directly as packed fp16 pairs */
        uint32_t pe[8][2];
#pragma unroll
        for (int j = 0; j < 8; j++) {
            pe[j][0] = ex2_h2(s[j][0] - mn0, s[j][1] - mn0);
            pe[j][1] = ex2_h2(s[j][2] - mn1, s[j][3] - mn1);
        }
#pragma unroll
        for (int j = 0; j < 9; j++) {
            o[j][0] *= corr0; o[j][1] *= corr0;
            o[j][2] *= corr1; o[j][3] *= corr1;
        }

        /* ---- O += P V (V frags via ldmatrix.trans), l += P·1 ---- */
#pragma unroll
        for (int k16 = 0; k16 < 4; k16++) {
            uint32_t pa[4];
            pa[0] = pe[2 * k16][0];
            pa[1] = pe[2 * k16][1];
            pa[2] = pe[2 * k16 + 1][0];
            pa[3] = pe[2 * k16 + 1][1];
            uint32_t vb[8][2];
#pragma unroll
            for (int t = 0; t < 4; t++) {
                uint32_t d0, d1, d2, d3;
                LDSM4T(d0, d1, d2, d3, vbase + vm_base[t] + (uint32_t)k16 * 16 * AT_ROWB);
                vb[2 * t][0] = d0;     vb[2 * t][1] = d1;
                vb[2 * t + 1][0] = d2; vb[2 * t + 1][1] = d3;
            }
#pragma unroll
            for (int j = 0; j < 8; j++)
                MMA_F16(o[j], pa, vb[j][0], vb[j][1]);
            MMA_F16(o[8], pa, H2_ONES, H2_ONES);
        }
    }

    /* epilogue: l from ones column; normalize; write ctx fp16 [B*S, D] */
    const int b_ = bh >> 4, h = bh & (HH - 1);
    const float inv0 = 1.0f / o[8][0], inv1 = 1.0f / o[8][2];
    const int s0 = qt * 64 + mrow + ar, s1 = s0 + 8;
    __half* p0 = g_ctx + (size_t)(b_ * SS + s0) * DD + h * DHD;
    __half* p1 = g_ctx + (size_t)(b_ * SS + s1) * DD + h * DHD;
#pragma unroll
    for (int j = 0; j < 8; j++) {
        const int c = j * 8 + 2 * ac;
        *reinterpret_cast<__half2*>(&p0[c]) =
            __floats2half2_rn(o[j][0] * inv0, o[j][1] * inv0);
        *reinterpret_cast<__half2*>(&p1[c]) =
            __floats2half2_rn(o[j][2] * inv1, o[j][3] * inv1);
    }
}

/* ------------------------------------------------------------------ */
extern "C" void kernel_launch(void* const* d_in, const int* in_sizes, int n_in,
                              void* d_out, int out_size)
{
    (void)in_sizes; (void)n_in; (void)out_size;
    const float* x  = (const float*)d_in[0];
    const float* Wq = (const float*)d_in[1];
    const float* Wk = (const float*)d_in[2];
    const float* Wv = (const float*)d_in[3];
    const float* Wo = (const float*)d_in[4];
    const float* bo = (const float*)d_in[5];
    float* out = (float*)d_out;

    cudaFuncSetAttribute(qkv_h_kernel,  cudaFuncAttributeMaxDynamicSharedMemorySize, GM_SMEM);
    cudaFuncSetAttribute(out_h_kernel,  cudaFuncAttributeMaxDynamicSharedMemorySize, GM_SMEM);
    cudaFuncSetAttribute(attn_h_kernel, cudaFuncAttributeMaxDynamicSharedMemorySize, AT_SMEM);

    round_x_kernel<<<2048, 256>>>(x);
    wtrans_kernel<<<dim3(32, 32, 4), dim3(32, 8)>>>(Wq, Wk, Wv, Wo);

    dim3 gq(DD / 128, NROWS / 128, 3);
    qkv_h_kernel<<<gq, 128, GM_SMEM>>>();

    dim3 ga(SS / 64, BB * HH);
    attn_h_kernel<<<ga, 128, AT_SMEM>>>();

    dim3 go(DD / 128, NROWS / 128);
    out_h_kernel<<<go, 128, GM_SMEM>>>(bo, out);
}